// round 1
// baseline (speedup 1.0000x reference)
#include <cuda_runtime.h>
#include <cmath>

#define NB   8
#define NSEQ 4096
#define NC   768
#define NH   12
#define NHD  64
#define NM   32
#define NBH  (NB*NH)
#define NSPLIT 8

// ---------------- scratch (device globals; no runtime allocation) ----------
__device__ float g_kqv[(size_t)3*NB*NH*NSEQ*NHD];   // [s][b][h][n][d]  302 MB
__device__ float g_kp [(size_t)NB*NH*NSEQ*NM];      // [b][h][n][m]
__device__ float g_qp [(size_t)NB*NH*NSEQ*NM];
__device__ float g_kptv_part [(size_t)NSPLIT*NBH*NHD*NM];
__device__ float g_kpsum_part[(size_t)NSPLIT*NBH*NM];
__device__ float g_kptv [(size_t)NBH*NHD*NM];       // [bh][d][m]
__device__ float g_kpsum[(size_t)NBH*NM];
__device__ float g_y[(size_t)NB*NSEQ*NC];           // [b][n][h*64+d]

// ---------------- GEMM1: kqv = x @ kqv_w^T + b, scatter to k/q/v ----------
__global__ __launch_bounds__(256, 2)
void gemm_kqv_kernel(const float* __restrict__ A,
                     const float* __restrict__ W,
                     const float* __restrict__ bias)
{
    const int K = NC;
    __shared__ float As[16][128];
    __shared__ float Bs[16][128];
    int tid = threadIdx.x;
    int m0 = blockIdx.y * 128;
    int n0 = blockIdx.x * 128;
    int lr = tid >> 2;
    int lk = (tid & 3) << 2;
    int rm = (tid >> 4) << 3;
    int cn = (tid & 15) << 2;

    float acc[8][8];
#pragma unroll
    for (int i = 0; i < 8; i++)
#pragma unroll
        for (int j = 0; j < 8; j++) acc[i][j] = 0.f;

    const float* Ab = A + (size_t)m0 * K;
    const float* Wb = W + (size_t)n0 * K;

    for (int k0 = 0; k0 < K; k0 += 16) {
#pragma unroll
        for (int hh = 0; hh < 2; hh++) {
            int r = lr + hh * 64;
            float4 va = *(const float4*)(Ab + (size_t)r * K + k0 + lk);
            As[lk + 0][r] = va.x; As[lk + 1][r] = va.y;
            As[lk + 2][r] = va.z; As[lk + 3][r] = va.w;
            float4 vb = *(const float4*)(Wb + (size_t)r * K + k0 + lk);
            Bs[lk + 0][r] = vb.x; Bs[lk + 1][r] = vb.y;
            Bs[lk + 2][r] = vb.z; Bs[lk + 3][r] = vb.w;
        }
        __syncthreads();
#pragma unroll
        for (int k = 0; k < 16; k++) {
            float a[8], b[8];
            *(float4*)&a[0] = *(const float4*)&As[k][rm];
            *(float4*)&a[4] = *(const float4*)&As[k][rm + 4];
            *(float4*)&b[0] = *(const float4*)&Bs[k][cn];
            *(float4*)&b[4] = *(const float4*)&Bs[k][cn + 64];
#pragma unroll
            for (int i = 0; i < 8; i++)
#pragma unroll
                for (int j = 0; j < 8; j++) acc[i][j] += a[i] * b[j];
        }
        __syncthreads();
    }

#pragma unroll
    for (int i = 0; i < 8; i++) {
        int r  = m0 + rm + i;
        int bb = r >> 12;          // r / 4096
        int n  = r & (NSEQ - 1);
#pragma unroll
        for (int j = 0; j < 8; j++) {
            int c = n0 + cn + ((j < 4) ? j : (60 + j));
            float v = acc[i][j] + bias[c];
            int s   = c / NC;
            int rem = c - s * NC;
            int hh  = rem >> 6;
            int d   = rem & 63;
            size_t idx = ((((size_t)s * NB + bb) * NH + hh) * NSEQ + n) * NHD + d;
            g_kqv[idx] = v;
        }
    }
}

// ---------------- feature map: kp/qp = exp(w.x - 0.5||x||^2)/sqrt(M) -------
__global__ __launch_bounds__(256)
void feat_kernel(const float* __restrict__ w, int which)   // 0: k->kp, 1: q->qp
{
    __shared__ float ws[64][32];   // [d][m], conflict-free across lanes (m=lane)
    int h = blockIdx.y, b = blockIdx.z;
    for (int i = threadIdx.x; i < NM * NHD; i += 256) {
        int m = i >> 6, d = i & 63;
        ws[d][m] = w[(h * NM + m) * NHD + d];
    }
    __syncthreads();

    const size_t bh = (size_t)b * NH + h;
    const float* inp = (which == 0 ? g_kqv : g_kqv + (size_t)NB*NH*NSEQ*NHD)
                       + bh * NSEQ * NHD;
    float* outp = (which == 0 ? g_kp : g_qp) + bh * NSEQ * NM;

    int warp = threadIdx.x >> 5, lane = threadIdx.x & 31;
    const int RPW = 16;
    int nbase = (blockIdx.x * 8 + warp) * RPW;
    const float inv_sqrt_m = 0.17677669529663687f;   // 1/sqrt(32)

    for (int rr = 0; rr < RPW; rr++) {
        int n = nbase + rr;
        float k0 = inp[(size_t)n * NHD + lane];
        float k1 = inp[(size_t)n * NHD + 32 + lane];
        float sq = k0 * k0 + k1 * k1;
#pragma unroll
        for (int o = 16; o; o >>= 1) sq += __shfl_xor_sync(0xffffffffu, sq, o);
        float xd = 0.5f * sq;
        float acc = 0.f;
#pragma unroll
        for (int d = 0; d < 32; d++) {
            float kv = __shfl_sync(0xffffffffu, k0, d);
            acc += ws[d][lane] * kv;
        }
#pragma unroll
        for (int d = 0; d < 32; d++) {
            float kv = __shfl_sync(0xffffffffu, k1, d);
            acc += ws[32 + d][lane] * kv;
        }
        outp[(size_t)n * NM + lane] = expf(acc - xd) * inv_sqrt_m;
    }
}

// ---------------- kptv partials + kpsum partials (split-K, no atomics) ----
__global__ __launch_bounds__(256)
void kptv_kernel()
{
    int split = blockIdx.x, h = blockIdx.y, b = blockIdx.z;
    const int CH = NSEQ / NSPLIT;          // 512 rows per split
    size_t bh = (size_t)b * NH + h;
    const float* vb = g_kqv + (size_t)2*NB*NH*NSEQ*NHD + bh*NSEQ*NHD + (size_t)split*CH*NHD;
    const float* kb = g_kp  + bh*NSEQ*NM + (size_t)split*CH*NM;

    __shared__ float vs[16][64];
    __shared__ float ks[16][32];
    int m  = threadIdx.x & 31;
    int dg = threadIdx.x >> 5;             // warp id 0..7 -> d group
    float acc[8];
#pragma unroll
    for (int i = 0; i < 8; i++) acc[i] = 0.f;
    float sacc = 0.f;

    for (int n0 = 0; n0 < CH; n0 += 16) {
        __syncthreads();
        for (int i = threadIdx.x; i < 16 * 64; i += 256)
            vs[i >> 6][i & 63] = vb[(size_t)n0 * NHD + i];
        for (int i = threadIdx.x; i < 16 * 32; i += 256)
            ks[i >> 5][i & 31] = kb[(size_t)n0 * NM + i];
        __syncthreads();
#pragma unroll
        for (int n = 0; n < 16; n++) {
            float kv = ks[n][m];
            if (dg == 0) sacc += kv;
            float4 v0 = *(const float4*)&vs[n][dg * 8];
            float4 v1 = *(const float4*)&vs[n][dg * 8 + 4];
            acc[0] += kv * v0.x; acc[1] += kv * v0.y;
            acc[2] += kv * v0.z; acc[3] += kv * v0.w;
            acc[4] += kv * v1.x; acc[5] += kv * v1.y;
            acc[6] += kv * v1.z; acc[7] += kv * v1.w;
        }
    }
    float* kout = g_kptv_part + ((size_t)split * NBH + bh) * (NHD * NM);
#pragma unroll
    for (int i = 0; i < 8; i++)
        kout[(dg * 8 + i) * NM + m] = acc[i];
    if (dg == 0)
        g_kpsum_part[((size_t)split * NBH + bh) * NM + m] = sacc;
}

// ---------------- reduce split-K partials (deterministic) ------------------
__global__ __launch_bounds__(256)
void reduce_kernel()
{
    int idx = blockIdx.x * 256 + threadIdx.x;
    const int TOT = NBH * NHD * NM;        // 196608
    if (idx < TOT) {
        float s = 0.f;
#pragma unroll
        for (int p = 0; p < NSPLIT; p++) s += g_kptv_part[(size_t)p * TOT + idx];
        g_kptv[idx] = s;
    }
    if (idx < NBH * NM) {
        float s = 0.f;
#pragma unroll
        for (int p = 0; p < NSPLIT; p++) s += g_kpsum_part[(size_t)p * NBH * NM + idx];
        g_kpsum[idx] = s;
    }
}

// ---------------- y = (qp @ kptv^T) / (qp.kpsum + eps), fused transpose ----
__global__ __launch_bounds__(256)
void attn_kernel()
{
    int h = blockIdx.y, b = blockIdx.z;
    size_t bh = (size_t)b * NH + h;
    __shared__ float ksh[64][33];          // padded: lanes read distinct d rows
    __shared__ float ssh[32];
    for (int i = threadIdx.x; i < NHD * NM; i += 256)
        ksh[i >> 5][i & 31] = g_kptv[bh * (NHD * NM) + i];
    if (threadIdx.x < 32) ssh[threadIdx.x] = g_kpsum[bh * NM + threadIdx.x];
    __syncthreads();

    int warp = threadIdx.x >> 5, lane = threadIdx.x & 31;
    const int RPW = 8;
    int nbase = (blockIdx.x * 8 + warp) * RPW;
    const float* qb = g_qp + bh * NSEQ * NM;

    for (int rr = 0; rr < RPW; rr++) {
        int n = nbase + rr;
        float qv = qb[(size_t)n * NM + lane];
        float a0 = 0.f, a1 = 0.f, Dv = 0.f;
#pragma unroll
        for (int mm = 0; mm < 32; mm++) {
            float q = __shfl_sync(0xffffffffu, qv, mm);
            a0 += q * ksh[lane][mm];
            a1 += q * ksh[lane + 32][mm];
            Dv += q * ssh[mm];
        }
        float inv = 1.0f / (Dv + 1e-8f);
        float* yo = g_y + ((size_t)b * NSEQ + n) * NC + h * NHD;
        yo[lane]      = a0 * inv;
        yo[lane + 32] = a1 * inv;
    }
}

// ---------------- GEMM2: out = y @ proj_w^T + proj_b -----------------------
__global__ __launch_bounds__(256, 2)
void gemm_proj_kernel(const float* __restrict__ W,
                      const float* __restrict__ bias,
                      float* __restrict__ out)
{
    const int K = NC;
    __shared__ float As[16][128];
    __shared__ float Bs[16][128];
    int tid = threadIdx.x;
    int m0 = blockIdx.y * 128;
    int n0 = blockIdx.x * 128;
    int lr = tid >> 2;
    int lk = (tid & 3) << 2;
    int rm = (tid >> 4) << 3;
    int cn = (tid & 15) << 2;

    float acc[8][8];
#pragma unroll
    for (int i = 0; i < 8; i++)
#pragma unroll
        for (int j = 0; j < 8; j++) acc[i][j] = 0.f;

    const float* Ab = g_y + (size_t)m0 * K;
    const float* Wb = W + (size_t)n0 * K;

    for (int k0 = 0; k0 < K; k0 += 16) {
#pragma unroll
        for (int hh = 0; hh < 2; hh++) {
            int r = lr + hh * 64;
            float4 va = *(const float4*)(Ab + (size_t)r * K + k0 + lk);
            As[lk + 0][r] = va.x; As[lk + 1][r] = va.y;
            As[lk + 2][r] = va.z; As[lk + 3][r] = va.w;
            float4 vb = *(const float4*)(Wb + (size_t)r * K + k0 + lk);
            Bs[lk + 0][r] = vb.x; Bs[lk + 1][r] = vb.y;
            Bs[lk + 2][r] = vb.z; Bs[lk + 3][r] = vb.w;
        }
        __syncthreads();
#pragma unroll
        for (int k = 0; k < 16; k++) {
            float a[8], b[8];
            *(float4*)&a[0] = *(const float4*)&As[k][rm];
            *(float4*)&a[4] = *(const float4*)&As[k][rm + 4];
            *(float4*)&b[0] = *(const float4*)&Bs[k][cn];
            *(float4*)&b[4] = *(const float4*)&Bs[k][cn + 64];
#pragma unroll
            for (int i = 0; i < 8; i++)
#pragma unroll
                for (int j = 0; j < 8; j++) acc[i][j] += a[i] * b[j];
        }
        __syncthreads();
    }

#pragma unroll
    for (int i = 0; i < 8; i++) {
        int r = m0 + rm + i;
#pragma unroll
        for (int j = 0; j < 8; j++) {
            int c = n0 + cn + ((j < 4) ? j : (60 + j));
            out[(size_t)r * NC + c] = acc[i][j] + bias[c];
        }
    }
}

// ---------------- launcher -------------------------------------------------
extern "C" void kernel_launch(void* const* d_in, const int* in_sizes, int n_in,
                              void* d_out, int out_size)
{
    const float* x      = (const float*)d_in[0];
    const float* kqv_w  = (const float*)d_in[1];
    const float* kqv_b  = (const float*)d_in[2];
    const float* proj_w = (const float*)d_in[3];
    const float* proj_b = (const float*)d_in[4];
    const float* w      = (const float*)d_in[5];
    float* out = (float*)d_out;

    gemm_kqv_kernel<<<dim3(3 * NC / 128, NB * NSEQ / 128), 256>>>(x, kqv_w, kqv_b);
    feat_kernel<<<dim3(NSEQ / 128, NH, NB), 256>>>(w, 0);
    feat_kernel<<<dim3(NSEQ / 128, NH, NB), 256>>>(w, 1);
    kptv_kernel<<<dim3(NSPLIT, NH, NB), 256>>>();
    reduce_kernel<<<(NBH * NHD * NM + 255) / 256, 256>>>();
    attn_kernel<<<dim3(NSEQ / 64, NH, NB), 256>>>();
    gemm_proj_kernel<<<dim3(NC / 128, NB * NSEQ / 128), 256>>>(proj_w, proj_b, out);
}

// round 3
// speedup vs baseline: 2.1505x; 2.1505x over previous
#include <cuda_runtime.h>
#include <cuda_fp16.h>
#include <cstdint>
#include <cmath>

#define NB   8
#define NSEQ 4096
#define NC   768
#define NH   12
#define NHD  64
#define NM   32
#define NBH  (NB*NH)
#define NSPLIT 8

// ---------------- scratch (device globals; no runtime allocation) ----------
__device__ float g_kqv[(size_t)3*NB*NH*NSEQ*NHD];   // [s][b][h][n][d]
__device__ float g_kp [(size_t)NB*NH*NSEQ*NM];
__device__ float g_qp [(size_t)NB*NH*NSEQ*NM];
__device__ float g_kptv_part [(size_t)NSPLIT*NBH*NHD*NM];
__device__ float g_kpsum_part[(size_t)NSPLIT*NBH*NM];
__device__ float g_kptv [(size_t)NBH*NHD*NM];
__device__ float g_kpsum[(size_t)NBH*NM];
__device__ __half g_xh[(size_t)NB*NSEQ*NC];
__device__ __half g_xl[(size_t)NB*NSEQ*NC];
__device__ __half g_yh[(size_t)NB*NSEQ*NC];
__device__ __half g_yl[(size_t)NB*NSEQ*NC];
__device__ __half g_w1h[(size_t)3*NC*NC];
__device__ __half g_w1l[(size_t)3*NC*NC];
__device__ __half g_w2h[(size_t)NC*NC];
__device__ __half g_w2l[(size_t)NC*NC];

// ---------------- PTX helpers ---------------------------------------------
__device__ __forceinline__ uint32_t smem_u32(const void* p) {
    return (uint32_t)__cvta_generic_to_shared(p);
}
__device__ __forceinline__ void cp16(uint32_t dst, const void* src) {
    asm volatile("cp.async.cg.shared.global [%0], [%1], 16;\n" :: "r"(dst), "l"(src));
}
#define CP_COMMIT() asm volatile("cp.async.commit_group;\n" ::: "memory")

#define LDMX4(r, a) \
    asm volatile("ldmatrix.sync.aligned.m8n8.x4.shared.b16 {%0,%1,%2,%3}, [%4];" \
        : "=r"((r)[0]), "=r"((r)[1]), "=r"((r)[2]), "=r"((r)[3]) : "r"(a))

#define MMA16816(acc, A, B0, B1) \
    asm volatile("mma.sync.aligned.m16n8k16.row.col.f32.f16.f16.f32 " \
        "{%0,%1,%2,%3},{%4,%5,%6,%7},{%8,%9},{%0,%1,%2,%3};" \
        : "+f"((acc)[0]), "+f"((acc)[1]), "+f"((acc)[2]), "+f"((acc)[3]) \
        : "r"((A)[0]), "r"((A)[1]), "r"((A)[2]), "r"((A)[3]), "r"(B0), "r"(B1))

// smem tile layout: 128 rows x 32 halves (64B/row); chunk swizzle keeps both
// cp.async stores and ldmatrix 8-row groups bank-conflict-free.
__device__ __forceinline__ uint32_t swz_off(int row, int g) {
    return (uint32_t)(row * 64 + ((g ^ ((row >> 1) & 3)) << 4));
}

// ---------------- tensor-core GEMM (hi/lo fp16 split, merged accum) --------
#define BM 128
#define BN 128
#define BK 32
#define NKIT (NC/BK)          // 24
#define TILE_B 8192           // one 128x32 fp16 tile
#define STAGE_B (4*TILE_B)    // Ah, Al, Bh, Bl
#define DYN_SMEM (2*STAGE_B)  // 64 KB

__global__ __launch_bounds__(256)
void gemm_tc(const __half* __restrict__ Ah, const __half* __restrict__ Al,
             const __half* __restrict__ Bh, const __half* __restrict__ Bl,
             const float* __restrict__ bias, float* __restrict__ out, int mode)
{
    extern __shared__ char smem[];
    uint32_t sb = smem_u32(smem);
    int tid = threadIdx.x, wid = tid >> 5, lane = tid & 31;
    int m0 = blockIdx.y * BM, n0 = blockIdx.x * BN;
    int wm = wid & 1;          // 2 m-halves of 64
    int wn = wid >> 1;         // 4 n-quarters of 32

    float acc[4][4][4];
#pragma unroll
    for (int i = 0; i < 4; i++)
#pragma unroll
        for (int j = 0; j < 4; j++)
#pragma unroll
            for (int t = 0; t < 4; t++) acc[i][j][t] = 0.f;

    auto load_stage = [&](int c, int st) {
        int k0 = c * BK;
        uint32_t base = sb + st * STAGE_B;
#pragma unroll
        for (int i = 0; i < 2; i++) {
            int cc = tid + i * 256;
            int row = cc >> 2, g = cc & 3;
            uint32_t off = swz_off(row, g);
            size_t asrc = (size_t)(m0 + row) * NC + k0 + g * 8;
            size_t bsrc = (size_t)(n0 + row) * NC + k0 + g * 8;
            cp16(base + off,              Ah + asrc);
            cp16(base + TILE_B + off,     Al + asrc);
            cp16(base + 2 * TILE_B + off, Bh + bsrc);
            cp16(base + 3 * TILE_B + off, Bl + bsrc);
        }
        CP_COMMIT();
    };

    load_stage(0, 0);
    load_stage(1, 1);

    for (int c = 0; c < NKIT; c++) {
        int st = c & 1;
        if (c < NKIT - 1) asm volatile("cp.async.wait_group 1;\n" ::: "memory");
        else              asm volatile("cp.async.wait_group 0;\n" ::: "memory");
        __syncthreads();

        uint32_t baseA  = sb + st * STAGE_B;
        uint32_t baseAl = baseA + TILE_B;
        uint32_t baseB  = baseA + 2 * TILE_B;
        uint32_t baseBl = baseA + 3 * TILE_B;

#pragma unroll
        for (int kt = 0; kt < 2; kt++) {
            uint32_t ah[4][4], al[4][4], bh[4][2], bl[4][2];
            int gA = kt * 2 + (lane >> 4);
#pragma unroll
            for (int mt = 0; mt < 4; mt++) {
                int row = wm * 64 + mt * 16 + (lane & 15);
                uint32_t off = swz_off(row, gA);
                LDMX4(ah[mt], baseA + off);
                LDMX4(al[mt], baseAl + off);
            }
            int gB = kt * 2 + ((lane >> 3) & 1);
#pragma unroll
            for (int np = 0; np < 2; np++) {
                int row = wn * 32 + np * 16 + (lane & 7) + ((lane >> 4) << 3);
                uint32_t off = swz_off(row, gB);
                uint32_t t0[4], t1[4];
                LDMX4(t0, baseB + off);
                LDMX4(t1, baseBl + off);
                bh[np*2][0] = t0[0]; bh[np*2][1] = t0[1];
                bh[np*2+1][0] = t0[2]; bh[np*2+1][1] = t0[3];
                bl[np*2][0] = t1[0]; bl[np*2][1] = t1[1];
                bl[np*2+1][0] = t1[2]; bl[np*2+1][1] = t1[3];
            }
#pragma unroll
            for (int mt = 0; mt < 4; mt++)
#pragma unroll
                for (int nt = 0; nt < 4; nt++) {
                    MMA16816(acc[mt][nt], ah[mt], bh[nt][0], bh[nt][1]);
                    MMA16816(acc[mt][nt], ah[mt], bl[nt][0], bl[nt][1]);
                    MMA16816(acc[mt][nt], al[mt], bh[nt][0], bh[nt][1]);
                }
        }
        __syncthreads();
        if (c + 2 < NKIT) load_stage(c + 2, st);
    }

    // ---- epilogue: bias + scatter (mode 0: kqv split; mode 1: plain) -----
    int row_in = lane >> 2, col2 = (lane & 3) * 2;
#pragma unroll
    for (int mt = 0; mt < 4; mt++) {
        int r0 = m0 + wm * 64 + mt * 16 + row_in;
        int r1 = r0 + 8;
#pragma unroll
        for (int nt = 0; nt < 4; nt++) {
            int col = n0 + wn * 32 + nt * 8 + col2;
            float b0 = bias[col], b1 = bias[col + 1];
            float2 v0 = make_float2(acc[mt][nt][0] + b0, acc[mt][nt][1] + b1);
            float2 v1 = make_float2(acc[mt][nt][2] + b0, acc[mt][nt][3] + b1);
            if (mode == 0) {
                int s = col / NC, rem = col - s * NC;
                int hh = rem >> 6, d = rem & 63;
                int bb0 = r0 >> 12, nn0 = r0 & (NSEQ - 1);
                int bb1 = r1 >> 12, nn1 = r1 & (NSEQ - 1);
                *(float2*)&g_kqv[((((size_t)s*NB+bb0)*NH+hh)*NSEQ+nn0)*NHD + d] = v0;
                *(float2*)&g_kqv[((((size_t)s*NB+bb1)*NH+hh)*NSEQ+nn1)*NHD + d] = v1;
            } else {
                *(float2*)&out[(size_t)r0 * NC + col] = v0;
                *(float2*)&out[(size_t)r1 * NC + col] = v1;
            }
        }
    }
}

// ---------------- fp32 -> fp16 hi/lo (lo unscaled) -------------------------
__global__ __launch_bounds__(256)
void convert_hilo(const float* __restrict__ in, __half* __restrict__ hi,
                  __half* __restrict__ lo, int n4)
{
    int i = blockIdx.x * 256 + threadIdx.x;
    if (i >= n4) return;
    float4 v = ((const float4*)in)[i];
    __half h0 = __float2half_rn(v.x), h1 = __float2half_rn(v.y);
    __half h2 = __float2half_rn(v.z), h3 = __float2half_rn(v.w);
    __half l0 = __float2half_rn(v.x - __half2float(h0));
    __half l1 = __float2half_rn(v.y - __half2float(h1));
    __half l2 = __float2half_rn(v.z - __half2float(h2));
    __half l3 = __float2half_rn(v.w - __half2float(h3));
    __half2* H = (__half2*)hi;
    __half2* L = (__half2*)lo;
    H[2*i]   = __halves2half2(h0, h1);
    H[2*i+1] = __halves2half2(h2, h3);
    L[2*i]   = __halves2half2(l0, l1);
    L[2*i+1] = __halves2half2(l2, l3);
}

// ---------------- feature map ----------------------------------------------
__global__ __launch_bounds__(256)
void feat_kernel(const float* __restrict__ w, int which)
{
    __shared__ float ws[64][32];
    int h = blockIdx.y, b = blockIdx.z;
    for (int i = threadIdx.x; i < NM * NHD; i += 256) {
        int m = i >> 6, d = i & 63;
        ws[d][m] = w[(h * NM + m) * NHD + d];
    }
    __syncthreads();

    const size_t bh = (size_t)b * NH + h;
    const float* inp = (which == 0 ? g_kqv : g_kqv + (size_t)NB*NH*NSEQ*NHD)
                       + bh * NSEQ * NHD;
    float* outp = (which == 0 ? g_kp : g_qp) + bh * NSEQ * NM;

    int warp = threadIdx.x >> 5, lane = threadIdx.x & 31;
    const int RPW = 16;
    int nbase = (blockIdx.x * 8 + warp) * RPW;
    const float inv_sqrt_m = 0.17677669529663687f;

    for (int rr = 0; rr < RPW; rr++) {
        int n = nbase + rr;
        float k0 = inp[(size_t)n * NHD + lane];
        float k1 = inp[(size_t)n * NHD + 32 + lane];
        float sq = k0 * k0 + k1 * k1;
#pragma unroll
        for (int o = 16; o; o >>= 1) sq += __shfl_xor_sync(0xffffffffu, sq, o);
        float xd = 0.5f * sq;
        float acc = 0.f;
#pragma unroll
        for (int d = 0; d < 32; d++) {
            float kv = __shfl_sync(0xffffffffu, k0, d);
            acc += ws[d][lane] * kv;
        }
#pragma unroll
        for (int d = 0; d < 32; d++) {
            float kv = __shfl_sync(0xffffffffu, k1, d);
            acc += ws[32 + d][lane] * kv;
        }
        outp[(size_t)n * NM + lane] = expf(acc - xd) * inv_sqrt_m;
    }
}

// ---------------- kptv + kpsum (split-K) ------------------------------------
__global__ __launch_bounds__(256)
void kptv_kernel()
{
    int split = blockIdx.x, h = blockIdx.y, b = blockIdx.z;
    const int CH = NSEQ / NSPLIT;
    size_t bh = (size_t)b * NH + h;
    const float* vb = g_kqv + (size_t)2*NB*NH*NSEQ*NHD + bh*NSEQ*NHD + (size_t)split*CH*NHD;
    const float* kb = g_kp  + bh*NSEQ*NM + (size_t)split*CH*NM;

    __shared__ float vs[16][64];
    __shared__ float ks[16][32];
    int m  = threadIdx.x & 31;
    int dg = threadIdx.x >> 5;
    float acc[8];
#pragma unroll
    for (int i = 0; i < 8; i++) acc[i] = 0.f;
    float sacc = 0.f;

    for (int n0 = 0; n0 < CH; n0 += 16) {
        __syncthreads();
        for (int i = threadIdx.x; i < 16 * 64; i += 256)
            vs[i >> 6][i & 63] = vb[(size_t)n0 * NHD + i];
        for (int i = threadIdx.x; i < 16 * 32; i += 256)
            ks[i >> 5][i & 31] = kb[(size_t)n0 * NM + i];
        __syncthreads();
#pragma unroll
        for (int n = 0; n < 16; n++) {
            float kv = ks[n][m];
            if (dg == 0) sacc += kv;
            float4 v0 = *(const float4*)&vs[n][dg * 8];
            float4 v1 = *(const float4*)&vs[n][dg * 8 + 4];
            acc[0] += kv * v0.x; acc[1] += kv * v0.y;
            acc[2] += kv * v0.z; acc[3] += kv * v0.w;
            acc[4] += kv * v1.x; acc[5] += kv * v1.y;
            acc[6] += kv * v1.z; acc[7] += kv * v1.w;
        }
    }
    float* kout = g_kptv_part + ((size_t)split * NBH + bh) * (NHD * NM);
#pragma unroll
    for (int i = 0; i < 8; i++)
        kout[(dg * 8 + i) * NM + m] = acc[i];
    if (dg == 0)
        g_kpsum_part[((size_t)split * NBH + bh) * NM + m] = sacc;
}

__global__ __launch_bounds__(256)
void reduce_kernel()
{
    int idx = blockIdx.x * 256 + threadIdx.x;
    const int TOT = NBH * NHD * NM;
    if (idx < TOT) {
        float s = 0.f;
#pragma unroll
        for (int p = 0; p < NSPLIT; p++) s += g_kptv_part[(size_t)p * TOT + idx];
        g_kptv[idx] = s;
    }
    if (idx < NBH * NM) {
        float s = 0.f;
#pragma unroll
        for (int p = 0; p < NSPLIT; p++) s += g_kpsum_part[(size_t)p * NBH * NM + idx];
        g_kpsum[idx] = s;
    }
}

// ---------------- y = (qp @ kptv^T)/(D+eps), writes fp16 hi/lo --------------
__global__ __launch_bounds__(256)
void attn_kernel()
{
    int h = blockIdx.y, b = blockIdx.z;
    size_t bh = (size_t)b * NH + h;
    __shared__ float ksh[64][33];
    __shared__ float ssh[32];
    for (int i = threadIdx.x; i < NHD * NM; i += 256)
        ksh[i >> 5][i & 31] = g_kptv[bh * (NHD * NM) + i];
    if (threadIdx.x < 32) ssh[threadIdx.x] = g_kpsum[bh * NM + threadIdx.x];
    __syncthreads();

    int warp = threadIdx.x >> 5, lane = threadIdx.x & 31;
    const int RPW = 8;
    int nbase = (blockIdx.x * 8 + warp) * RPW;
    const float* qb = g_qp + bh * NSEQ * NM;

    for (int rr = 0; rr < RPW; rr++) {
        int n = nbase + rr;
        float qv = qb[(size_t)n * NM + lane];
        float a0 = 0.f, a1 = 0.f, Dv = 0.f;
#pragma unroll
        for (int mm = 0; mm < 32; mm++) {
            float q = __shfl_sync(0xffffffffu, qv, mm);
            a0 += q * ksh[lane][mm];
            a1 += q * ksh[lane + 32][mm];
            Dv += q * ssh[mm];
        }
        float inv = 1.0f / (Dv + 1e-8f);
        float y0 = a0 * inv, y1 = a1 * inv;
        size_t base = ((size_t)b * NSEQ + n) * NC + h * NHD;
        __half h0 = __float2half_rn(y0);
        __half h1 = __float2half_rn(y1);
        g_yh[base + lane]      = h0;
        g_yh[base + 32 + lane] = h1;
        g_yl[base + lane]      = __float2half_rn(y0 - __half2float(h0));
        g_yl[base + 32 + lane] = __float2half_rn(y1 - __half2float(h1));
    }
}

// ---------------- launcher --------------------------------------------------
extern "C" void kernel_launch(void* const* d_in, const int* in_sizes, int n_in,
                              void* d_out, int out_size)
{
    const float* x      = (const float*)d_in[0];
    const float* kqv_w  = (const float*)d_in[1];
    const float* kqv_b  = (const float*)d_in[2];
    const float* proj_w = (const float*)d_in[3];
    const float* proj_b = (const float*)d_in[4];
    const float* w      = (const float*)d_in[5];
    float* out = (float*)d_out;

    void* p;
    cudaGetSymbolAddress(&p, g_xh);  __half* xh  = (__half*)p;
    cudaGetSymbolAddress(&p, g_xl);  __half* xl  = (__half*)p;
    cudaGetSymbolAddress(&p, g_yh);  __half* yh  = (__half*)p;
    cudaGetSymbolAddress(&p, g_yl);  __half* yl  = (__half*)p;
    cudaGetSymbolAddress(&p, g_w1h); __half* w1h = (__half*)p;
    cudaGetSymbolAddress(&p, g_w1l); __half* w1l = (__half*)p;
    cudaGetSymbolAddress(&p, g_w2h); __half* w2h = (__half*)p;
    cudaGetSymbolAddress(&p, g_w2l); __half* w2l = (__half*)p;

    cudaFuncSetAttribute(gemm_tc, cudaFuncAttributeMaxDynamicSharedMemorySize, DYN_SMEM);

    const int NX = NB * NSEQ * NC / 4;
    const int NW1 = 3 * NC * NC / 4;
    const int NW2 = NC * NC / 4;
    convert_hilo<<<(NX + 255) / 256, 256>>>(x, xh, xl, NX);
    convert_hilo<<<(NW1 + 255) / 256, 256>>>(kqv_w, w1h, w1l, NW1);
    convert_hilo<<<(NW2 + 255) / 256, 256>>>(proj_w, w2h, w2l, NW2);

    gemm_tc<<<dim3(3 * NC / BN, NB * NSEQ / BM), 256, DYN_SMEM>>>(
        xh, xl, w1h, w1l, kqv_b, nullptr, 0);

    feat_kernel<<<dim3(NSEQ / 128, NH, NB), 256>>>(w, 0);
    feat_kernel<<<dim3(NSEQ / 128, NH, NB), 256>>>(w, 1);
    kptv_kernel<<<dim3(NSPLIT, NH, NB), 256>>>();
    reduce_kernel<<<(NBH * NHD * NM + 255) / 256, 256>>>();
    attn_kernel<<<dim3(NSEQ / 64, NH, NB), 256>>>();

    gemm_tc<<<dim3(NC / BN, NB * NSEQ / BM), 256, DYN_SMEM>>>(
        yh, yl, w2h, w2l, proj_b, out, 1);
}

// round 4
// speedup vs baseline: 2.1875x; 1.0172x over previous
#include <cuda_runtime.h>
#include <cuda_fp16.h>
#include <cstdint>
#include <cmath>

#define NB   8
#define NSEQ 4096
#define NC   768
#define NH   12
#define NHD  64
#define NM   32
#define NBH  (NB*NH)
#define NSPLIT 16

// ---------------- scratch (device globals; no runtime allocation) ----------
__device__ float g_kqv[(size_t)3*NB*NH*NSEQ*NHD];   // [s][b][h][n][d]
__device__ float g_kptv_part [(size_t)NSPLIT*NBH*NHD*NM];
__device__ float g_kpsum_part[(size_t)NSPLIT*NBH*NM];
__device__ float g_kptv [(size_t)NBH*NHD*NM];
__device__ float g_kpsum[(size_t)NBH*NM];
__device__ __half g_xh[(size_t)NB*NSEQ*NC];
__device__ __half g_xl[(size_t)NB*NSEQ*NC];
__device__ __half g_yh[(size_t)NB*NSEQ*NC];
__device__ __half g_yl[(size_t)NB*NSEQ*NC];
__device__ __half g_w1h[(size_t)3*NC*NC];
__device__ __half g_w1l[(size_t)3*NC*NC];
__device__ __half g_w2h[(size_t)NC*NC];
__device__ __half g_w2l[(size_t)NC*NC];

// ---------------- PTX helpers ---------------------------------------------
__device__ __forceinline__ uint32_t smem_u32(const void* p) {
    return (uint32_t)__cvta_generic_to_shared(p);
}
__device__ __forceinline__ void cp16(uint32_t dst, const void* src) {
    asm volatile("cp.async.cg.shared.global [%0], [%1], 16;\n" :: "r"(dst), "l"(src));
}
#define CP_COMMIT() asm volatile("cp.async.commit_group;\n" ::: "memory")

#define LDMX4(r, a) \
    asm volatile("ldmatrix.sync.aligned.m8n8.x4.shared.b16 {%0,%1,%2,%3}, [%4];" \
        : "=r"((r)[0]), "=r"((r)[1]), "=r"((r)[2]), "=r"((r)[3]) : "r"(a))

#define MMA16816(acc, A, B0, B1) \
    asm volatile("mma.sync.aligned.m16n8k16.row.col.f32.f16.f16.f32 " \
        "{%0,%1,%2,%3},{%4,%5,%6,%7},{%8,%9},{%0,%1,%2,%3};" \
        : "+f"((acc)[0]), "+f"((acc)[1]), "+f"((acc)[2]), "+f"((acc)[3]) \
        : "r"((A)[0]), "r"((A)[1]), "r"((A)[2]), "r"((A)[3]), "r"(B0), "r"(B1))

__device__ __forceinline__ uint32_t swz_off(int row, int g) {
    return (uint32_t)(row * 64 + ((g ^ ((row >> 1) & 3)) << 4));
}

// ---------------- tensor-core GEMM (hi/lo fp16 split, merged accum) --------
#define BM 128
#define BN 128
#define BK 32
#define NKIT (NC/BK)          // 24
#define TILE_B 8192
#define STAGE_B (4*TILE_B)    // Ah, Al, Bh, Bl  (32 KB)
#define NSTAGE 3
#define DYN_SMEM (NSTAGE*STAGE_B)  // 96 KB

__global__ __launch_bounds__(256)
void gemm_tc(const __half* __restrict__ Ah, const __half* __restrict__ Al,
             const __half* __restrict__ Bh, const __half* __restrict__ Bl,
             const float* __restrict__ bias, float* __restrict__ out, int mode)
{
    extern __shared__ char smem[];
    uint32_t sb = smem_u32(smem);
    int tid = threadIdx.x, wid = tid >> 5, lane = tid & 31;
    int m0 = blockIdx.y * BM, n0 = blockIdx.x * BN;
    int wm = wid & 1;
    int wn = wid >> 1;

    float acc[4][4][4];
#pragma unroll
    for (int i = 0; i < 4; i++)
#pragma unroll
        for (int j = 0; j < 4; j++)
#pragma unroll
            for (int t = 0; t < 4; t++) acc[i][j][t] = 0.f;

    auto load_stage = [&](int c, int st) {
        int k0 = c * BK;
        uint32_t base = sb + st * STAGE_B;
#pragma unroll
        for (int i = 0; i < 2; i++) {
            int cc = tid + i * 256;
            int row = cc >> 2, g = cc & 3;
            uint32_t off = swz_off(row, g);
            size_t asrc = (size_t)(m0 + row) * NC + k0 + g * 8;
            size_t bsrc = (size_t)(n0 + row) * NC + k0 + g * 8;
            cp16(base + off,              Ah + asrc);
            cp16(base + TILE_B + off,     Al + asrc);
            cp16(base + 2 * TILE_B + off, Bh + bsrc);
            cp16(base + 3 * TILE_B + off, Bl + bsrc);
        }
        CP_COMMIT();
    };

    load_stage(0, 0);
    load_stage(1, 1);

    for (int c = 0; c < NKIT; c++) {
        int st = c % NSTAGE;
        if (c + 2 < NKIT) asm volatile("cp.async.wait_group 1;\n" ::: "memory");
        else              asm volatile("cp.async.wait_group 0;\n" ::: "memory");
        __syncthreads();
        if (c + 2 < NKIT) load_stage(c + 2, (c + 2) % NSTAGE);

        uint32_t baseA  = sb + st * STAGE_B;
        uint32_t baseAl = baseA + TILE_B;
        uint32_t baseB  = baseA + 2 * TILE_B;
        uint32_t baseBl = baseA + 3 * TILE_B;

#pragma unroll
        for (int kt = 0; kt < 2; kt++) {
            uint32_t ah[4][4], al[4][4], bh[4][2], bl[4][2];
            int gA = kt * 2 + (lane >> 4);
#pragma unroll
            for (int mt = 0; mt < 4; mt++) {
                int row = wm * 64 + mt * 16 + (lane & 15);
                uint32_t off = swz_off(row, gA);
                LDMX4(ah[mt], baseA + off);
                LDMX4(al[mt], baseAl + off);
            }
            int gB = kt * 2 + ((lane >> 3) & 1);
#pragma unroll
            for (int np = 0; np < 2; np++) {
                int row = wn * 32 + np * 16 + (lane & 7) + ((lane >> 4) << 3);
                uint32_t off = swz_off(row, gB);
                uint32_t t0[4], t1[4];
                LDMX4(t0, baseB + off);
                LDMX4(t1, baseBl + off);
                bh[np*2][0] = t0[0]; bh[np*2][1] = t0[1];
                bh[np*2+1][0] = t0[2]; bh[np*2+1][1] = t0[3];
                bl[np*2][0] = t1[0]; bl[np*2][1] = t1[1];
                bl[np*2+1][0] = t1[2]; bl[np*2+1][1] = t1[3];
            }
#pragma unroll
            for (int mt = 0; mt < 4; mt++)
#pragma unroll
                for (int nt = 0; nt < 4; nt++) {
                    MMA16816(acc[mt][nt], ah[mt], bh[nt][0], bh[nt][1]);
                    MMA16816(acc[mt][nt], ah[mt], bl[nt][0], bl[nt][1]);
                    MMA16816(acc[mt][nt], al[mt], bh[nt][0], bh[nt][1]);
                }
        }
    }

    // ---- epilogue: bias + scatter (mode 0: kqv split; mode 1: plain) -----
    int row_in = lane >> 2, col2 = (lane & 3) * 2;
#pragma unroll
    for (int mt = 0; mt < 4; mt++) {
        int r0 = m0 + wm * 64 + mt * 16 + row_in;
        int r1 = r0 + 8;
#pragma unroll
        for (int nt = 0; nt < 4; nt++) {
            int col = n0 + wn * 32 + nt * 8 + col2;
            float b0 = bias[col], b1 = bias[col + 1];
            float2 v0 = make_float2(acc[mt][nt][0] + b0, acc[mt][nt][1] + b1);
            float2 v1 = make_float2(acc[mt][nt][2] + b0, acc[mt][nt][3] + b1);
            if (mode == 0) {
                int s = col / NC, rem = col - s * NC;
                int hh = rem >> 6, d = rem & 63;
                int bb0 = r0 >> 12, nn0 = r0 & (NSEQ - 1);
                int bb1 = r1 >> 12, nn1 = r1 & (NSEQ - 1);
                *(float2*)&g_kqv[((((size_t)s*NB+bb0)*NH+hh)*NSEQ+nn0)*NHD + d] = v0;
                *(float2*)&g_kqv[((((size_t)s*NB+bb1)*NH+hh)*NSEQ+nn1)*NHD + d] = v1;
            } else {
                *(float2*)&out[(size_t)r0 * NC + col] = v0;
                *(float2*)&out[(size_t)r1 * NC + col] = v1;
            }
        }
    }
}

// ---------------- fp32 -> fp16 hi/lo (lo unscaled) -------------------------
__global__ __launch_bounds__(256)
void convert_hilo(const float* __restrict__ in, __half* __restrict__ hi,
                  __half* __restrict__ lo, int n4)
{
    int i = blockIdx.x * 256 + threadIdx.x;
    if (i >= n4) return;
    float4 v = ((const float4*)in)[i];
    __half h0 = __float2half_rn(v.x), h1 = __float2half_rn(v.y);
    __half h2 = __float2half_rn(v.z), h3 = __float2half_rn(v.w);
    __half l0 = __float2half_rn(v.x - __half2float(h0));
    __half l1 = __float2half_rn(v.y - __half2float(h1));
    __half l2 = __float2half_rn(v.z - __half2float(h2));
    __half l3 = __float2half_rn(v.w - __half2float(h3));
    __half2* H = (__half2*)hi;
    __half2* L = (__half2*)lo;
    H[2*i]   = __halves2half2(h0, h1);
    H[2*i+1] = __halves2half2(h2, h3);
    L[2*i]   = __halves2half2(l0, l1);
    L[2*i+1] = __halves2half2(l2, l3);
}

#define INV_SQRT_M 0.17677669529663687f

// ---------------- fused feat(k) + kptv + kpsum (split-K) -------------------
__global__ __launch_bounds__(256)
void kptv_fused(const float* __restrict__ w)
{
    __shared__ float ws[64][33];
    __shared__ float kt[16][68];
    __shared__ float vs[16][64];
    __shared__ float ks[16][33];
    __shared__ float spart[8][33];

    int split = blockIdx.x, h = blockIdx.y, b = blockIdx.z;
    const int CH = NSEQ / NSPLIT;            // 256
    size_t bh = (size_t)b * NH + h;
    int tid = threadIdx.x, warp = tid >> 5, lane = tid & 31;

    // stage w[h] transposed: ws[d][m]
    for (int i = tid; i < NM * NHD; i += 256) {
        int m = i >> 6, d = i & 63;
        ws[d][m] = w[(h * NM + m) * NHD + d];
    }
    __syncthreads();
    float wreg[64];
#pragma unroll
    for (int d = 0; d < 64; d++) wreg[d] = ws[d][lane];   // lane = m

    const float* kbase = g_kqv + bh * NSEQ * NHD + (size_t)split * CH * NHD;
    const float* vbase = g_kqv + (size_t)2*NB*NH*NSEQ*NHD + bh * NSEQ * NHD
                         + (size_t)split * CH * NHD;

    float acc[8];
#pragma unroll
    for (int i = 0; i < 8; i++) acc[i] = 0.f;
    float sacc = 0.f;

    for (int n0 = 0; n0 < CH; n0 += 16) {
        __syncthreads();
        {   // 16 rows x 64 floats = 256 float4 each for k and v
            int row = tid >> 4, d4 = tid & 15;
            float4 kv4 = *(const float4*)(kbase + (size_t)(n0 + row) * NHD + d4 * 4);
            *(float4*)&kt[row][d4 * 4] = kv4;
            float4 vv4 = *(const float4*)(vbase + (size_t)(n0 + row) * NHD + d4 * 4);
            *(float4*)&vs[row][d4 * 4] = vv4;
        }
        __syncthreads();

        // compute kp tile: warp handles rows 2*warp, 2*warp+1; lane = m
#pragma unroll
        for (int rr = 0; rr < 2; rr++) {
            int row = warp * 2 + rr;
            float t0 = kt[row][lane], t1 = kt[row][lane + 32];
            float sq = t0 * t0 + t1 * t1;
#pragma unroll
            for (int o = 16; o; o >>= 1) sq += __shfl_xor_sync(0xffffffffu, sq, o);
            float xd = 0.5f * sq;
            float dot = 0.f;
#pragma unroll
            for (int d4 = 0; d4 < 16; d4++) {
                float4 kv = *(const float4*)&kt[row][d4 * 4];
                dot += wreg[d4*4+0] * kv.x;
                dot += wreg[d4*4+1] * kv.y;
                dot += wreg[d4*4+2] * kv.z;
                dot += wreg[d4*4+3] * kv.w;
            }
            float kp = expf(dot - xd) * INV_SQRT_M;
            ks[row][lane] = kp;
            sacc += kp;
        }
        __syncthreads();

        // accumulate: lane = m, warp = d-group of 8
#pragma unroll
        for (int n = 0; n < 16; n++) {
            float kv = ks[n][lane];
            float4 v0 = *(const float4*)&vs[n][warp * 8];
            float4 v1 = *(const float4*)&vs[n][warp * 8 + 4];
            acc[0] += kv * v0.x; acc[1] += kv * v0.y;
            acc[2] += kv * v0.z; acc[3] += kv * v0.w;
            acc[4] += kv * v1.x; acc[5] += kv * v1.y;
            acc[6] += kv * v1.z; acc[7] += kv * v1.w;
        }
    }

    float* kout = g_kptv_part + ((size_t)split * NBH + bh) * (NHD * NM);
#pragma unroll
    for (int i = 0; i < 8; i++)
        kout[(warp * 8 + i) * NM + lane] = acc[i];

    spart[warp][lane] = sacc;
    __syncthreads();
    if (warp == 0) {
        float s = 0.f;
#pragma unroll
        for (int p = 0; p < 8; p++) s += spart[p][lane];
        g_kpsum_part[((size_t)split * NBH + bh) * NM + lane] = s;
    }
}

__global__ __launch_bounds__(256)
void reduce_kernel()
{
    int idx = blockIdx.x * 256 + threadIdx.x;
    const int TOT = NBH * NHD * NM;
    if (idx < TOT) {
        float s = 0.f;
#pragma unroll
        for (int p = 0; p < NSPLIT; p++) s += g_kptv_part[(size_t)p * TOT + idx];
        g_kptv[idx] = s;
    }
    if (idx < NBH * NM) {
        float s = 0.f;
#pragma unroll
        for (int p = 0; p < NSPLIT; p++) s += g_kpsum_part[(size_t)p * NBH * NM + idx];
        g_kpsum[idx] = s;
    }
}

// ------- fused feat(q) + y = (qp @ kptv^T)/(D+eps), writes fp16 hi/lo ------
__global__ __launch_bounds__(256)
void attn_fused(const float* __restrict__ w)
{
    __shared__ float ws[64][33];
    __shared__ float ksh[64][33];
    __shared__ float ssh[32];
    __shared__ float qt[64][68];

    int h = blockIdx.y, b = blockIdx.z;
    size_t bh = (size_t)b * NH + h;
    int tid = threadIdx.x, warp = tid >> 5, lane = tid & 31;

    for (int i = tid; i < NM * NHD; i += 256) {
        int m = i >> 6, d = i & 63;
        ws[d][m] = w[(h * NM + m) * NHD + d];
    }
    for (int i = tid; i < NHD * NM; i += 256)
        ksh[i >> 5][i & 31] = g_kptv[bh * (NHD * NM) + i];
    if (tid < 32) ssh[tid] = g_kpsum[bh * NM + tid];
    __syncthreads();
    float wreg[64];
#pragma unroll
    for (int d = 0; d < 64; d++) wreg[d] = ws[d][lane];   // lane = m

    int ntile = blockIdx.x * 64;
    const float* qbase = g_kqv + (size_t)NB*NH*NSEQ*NHD + bh * NSEQ * NHD;

    // stage q tile: 64 rows x 64 floats = 1024 float4
#pragma unroll
    for (int i = 0; i < 4; i++) {
        int f4 = tid + i * 256;
        int row = f4 >> 4, d4 = f4 & 15;
        float4 v = *(const float4*)(qbase + (size_t)(ntile + row) * NHD + d4 * 4);
        *(float4*)&qt[row][d4 * 4] = v;
    }
    __syncthreads();

#pragma unroll
    for (int rr = 0; rr < 8; rr++) {
        int row = warp * 8 + rr;
        float t0 = qt[row][lane], t1 = qt[row][lane + 32];
        float sq = t0 * t0 + t1 * t1;
#pragma unroll
        for (int o = 16; o; o >>= 1) sq += __shfl_xor_sync(0xffffffffu, sq, o);
        float xd = 0.5f * sq;
        float dot = 0.f;
#pragma unroll
        for (int d4 = 0; d4 < 16; d4++) {
            float4 kv = *(const float4*)&qt[row][d4 * 4];
            dot += wreg[d4*4+0] * kv.x;
            dot += wreg[d4*4+1] * kv.y;
            dot += wreg[d4*4+2] * kv.z;
            dot += wreg[d4*4+3] * kv.w;
        }
        float qv = expf(dot - xd) * INV_SQRT_M;     // qp[row][lane]

        float a0 = 0.f, a1 = 0.f, Dv = 0.f;
#pragma unroll
        for (int mm = 0; mm < 32; mm++) {
            float q = __shfl_sync(0xffffffffu, qv, mm);
            a0 += q * ksh[lane][mm];
            a1 += q * ksh[lane + 32][mm];
            Dv += q * ssh[mm];
        }
        float inv = 1.0f / (Dv + 1e-8f);
        float y0 = a0 * inv, y1 = a1 * inv;
        size_t base = ((size_t)b * NSEQ + ntile + row) * NC + h * NHD;
        __half h0 = __float2half_rn(y0);
        __half h1 = __float2half_rn(y1);
        g_yh[base + lane]      = h0;
        g_yh[base + 32 + lane] = h1;
        g_yl[base + lane]      = __float2half_rn(y0 - __half2float(h0));
        g_yl[base + 32 + lane] = __float2half_rn(y1 - __half2float(h1));
    }
}

// ---------------- launcher --------------------------------------------------
extern "C" void kernel_launch(void* const* d_in, const int* in_sizes, int n_in,
                              void* d_out, int out_size)
{
    const float* x      = (const float*)d_in[0];
    const float* kqv_w  = (const float*)d_in[1];
    const float* kqv_b  = (const float*)d_in[2];
    const float* proj_w = (const float*)d_in[3];
    const float* proj_b = (const float*)d_in[4];
    const float* w      = (const float*)d_in[5];
    float* out = (float*)d_out;

    void* p;
    cudaGetSymbolAddress(&p, g_xh);  __half* xh  = (__half*)p;
    cudaGetSymbolAddress(&p, g_xl);  __half* xl  = (__half*)p;
    cudaGetSymbolAddress(&p, g_yh);  __half* yh  = (__half*)p;
    cudaGetSymbolAddress(&p, g_yl);  __half* yl  = (__half*)p;
    cudaGetSymbolAddress(&p, g_w1h); __half* w1h = (__half*)p;
    cudaGetSymbolAddress(&p, g_w1l); __half* w1l = (__half*)p;
    cudaGetSymbolAddress(&p, g_w2h); __half* w2h = (__half*)p;
    cudaGetSymbolAddress(&p, g_w2l); __half* w2l = (__half*)p;

    cudaFuncSetAttribute(gemm_tc, cudaFuncAttributeMaxDynamicSharedMemorySize, DYN_SMEM);

    const int NX = NB * NSEQ * NC / 4;
    const int NW1 = 3 * NC * NC / 4;
    const int NW2 = NC * NC / 4;
    convert_hilo<<<(NX + 255) / 256, 256>>>(x, xh, xl, NX);
    convert_hilo<<<(NW1 + 255) / 256, 256>>>(kqv_w, w1h, w1l, NW1);
    convert_hilo<<<(NW2 + 255) / 256, 256>>>(proj_w, w2h, w2l, NW2);

    gemm_tc<<<dim3(3 * NC / BN, NB * NSEQ / BM), 256, DYN_SMEM>>>(
        xh, xl, w1h, w1l, kqv_b, nullptr, 0);

    kptv_fused<<<dim3(NSPLIT, NH, NB), 256>>>(w);
    reduce_kernel<<<(NBH * NHD * NM + 255) / 256, 256>>>();
    attn_fused<<<dim3(NSEQ / 64, NH, NB), 256>>>(w);

    gemm_tc<<<dim3(NC / BN, NB * NSEQ / BM), 256, DYN_SMEM>>>(
        yh, yl, w2h, w2l, proj_b, out, 1);
}